// round 2
// baseline (speedup 1.0000x reference)
#include <cuda_runtime.h>
#include <cstdint>
#include <math.h>

// ---------------------------------------------------------------------------
// Problem constants (fixed by the reference)
// ---------------------------------------------------------------------------
#define N_NODESC 100000
#define N_EDGESC 400000
#define N_GRAPHSC 5000
#define F_INC 64
#define HC 128

// ---------------------------------------------------------------------------
// Scratch (device globals; no allocation allowed)
// ---------------------------------------------------------------------------
__device__ __align__(16) float g_h   [(size_t)N_NODESC * HC];   // current node features
__device__ __align__(16) float g_hs  [(size_t)N_NODESC * HC];   // h @ W (per layer)
__device__ __align__(16) float g_acc [(size_t)N_NODESC * HC];   // aggregation accumulator
__device__ __align__(16) float g_as  [N_NODESC];
__device__ __align__(16) float g_ad  [N_NODESC];
__device__ __align__(16) float g_ex  [N_EDGESC];
__device__ __align__(16) float g_den [N_NODESC];
__device__ __align__(16) float g_pooled[(size_t)N_GRAPHSC * HC];
__device__ __align__(16) float g_hd    [(size_t)N_GRAPHSC * HC];
__device__ __align__(16) float g_gacc  [(size_t)N_GRAPHSC * HC];
__device__ __align__(16) float g_asg [N_GRAPHSC];
__device__ __align__(16) float g_adg [N_GRAPHSC];
__device__ int g_i64flag[2];   // [0]: edge_index is int64, [1]: batch is int64

// ---------------------------------------------------------------------------
// dtype detection: reference declares int64 indices, but JAX may emit int32.
// Interpret the first 256 entries as int64; if all are in-range it is int64.
// (int32 data read as int64 packs two values; within 512 packed int32s the
// high word is >=1 for random edges and for sorted batch past graph 0, so
// the out-of-range test fires and classifies int32 correctly.)
// ---------------------------------------------------------------------------
__global__ void detect_kernel(const void* ei, const void* batch)
{
    int t = threadIdx.x;  // 256 threads
    const long long* p = (const long long*)ei;
    const long long* q = (const long long*)batch;
    long long v1 = p[t];
    long long v2 = q[t];
    int bad1 = (v1 < 0 || v1 >= N_NODESC) ? 1 : 0;
    int bad2 = (v2 < 0 || v2 >= N_GRAPHSC) ? 1 : 0;
    int any1 = __syncthreads_or(bad1);
    int any2 = __syncthreads_or(bad2);
    if (t == 0) {
        g_i64flag[0] = any1 ? 0 : 1;
        g_i64flag[1] = any2 ? 0 : 1;
    }
}

__device__ __forceinline__ int load_edge_idx(const void* ei, int i)
{
    if (g_i64flag[0]) return (int)((const long long*)ei)[i];
    return ((const int*)ei)[i];
}
__device__ __forceinline__ int load_batch_idx(const void* bp, int i)
{
    if (g_i64flag[1]) return (int)((const long long*)bp)[i];
    return ((const int*)bp)[i];
}

// ---------------------------------------------------------------------------
// GEMM: C[M,128] = A[M,K] @ W[K,128] (+ optional bias + leaky_relu)
// Block = 256 threads, tile 64 rows x 128 cols, K chunked by 32.
// Each thread owns a 4x8 register tile.
// Per k-step per warp: 2x LDS.128 (W) + 4x LDS.32 broadcast (A) = 12 crossbar
// cycles vs 64 SMSP cycles of FFMA -> FMA-pipe bound by design.
// ---------------------------------------------------------------------------
#define KC 32

template<int K, int ACT>   // ACT: 0 = none, 1 = +bias, leaky_relu(0.01)
__global__ void gemm_kernel(const float* __restrict__ A,
                            const float* __restrict__ W,
                            const float* __restrict__ bias,
                            float* __restrict__ C, int M)
{
    __shared__ float Ws[KC][HC];        // 32 x 128 = 16 KB
    __shared__ float As[64][36];        // 64 x 32 (+pad 4); row stride 144B (16B aligned)

    int t = threadIdx.x;
    int row0 = blockIdx.x * 64;
    int c0 = (t & 15) * 8;
    int r0 = (t >> 4) * 4;

    float acc[4][8];
#pragma unroll
    for (int r = 0; r < 4; r++)
#pragma unroll
        for (int c = 0; c < 8; c++) acc[r][c] = 0.f;

    for (int kc = 0; kc < K; kc += KC) {
        // load W chunk: 32 rows x 128 cols = 1024 float4
        const float4* Wg = (const float4*)(W + (size_t)kc * HC);
        float4* Ws4 = (float4*)Ws;
#pragma unroll
        for (int i = t; i < KC * HC / 4; i += 256) Ws4[i] = Wg[i];
        // load A chunk: 64 rows x 32 cols = 512 float4
#pragma unroll
        for (int i = t; i < 64 * KC / 4; i += 256) {
            int r = i >> 3;
            int j = i & 7;
            int row = row0 + r;
            float4 v = make_float4(0.f, 0.f, 0.f, 0.f);
            if (row < M) v = *(const float4*)(A + (size_t)row * K + kc + j * 4);
            *(float4*)(&As[r][j * 4]) = v;
        }
        __syncthreads();

#pragma unroll
        for (int k = 0; k < KC; k++) {
            float4 w0 = *(const float4*)(&Ws[k][c0]);
            float4 w1 = *(const float4*)(&Ws[k][c0 + 4]);
#pragma unroll
            for (int r = 0; r < 4; r++) {
                float a = As[r0 + r][k];
                acc[r][0] += a * w0.x; acc[r][1] += a * w0.y;
                acc[r][2] += a * w0.z; acc[r][3] += a * w0.w;
                acc[r][4] += a * w1.x; acc[r][5] += a * w1.y;
                acc[r][6] += a * w1.z; acc[r][7] += a * w1.w;
            }
        }
        __syncthreads();
    }

    float bv[8];
    if (ACT == 1) {
#pragma unroll
        for (int c = 0; c < 8; c++) bv[c] = bias[c0 + c];
    }
#pragma unroll
    for (int r = 0; r < 4; r++) {
        int row = row0 + r0 + r;
        if (row < M) {
            float* Crow = C + (size_t)row * HC + c0;
#pragma unroll
            for (int c = 0; c < 8; c += 4) {
                float4 v;
                v.x = acc[r][c + 0]; v.y = acc[r][c + 1];
                v.z = acc[r][c + 2]; v.w = acc[r][c + 3];
                if (ACT == 1) {
                    v.x += bv[c + 0]; v.y += bv[c + 1]; v.z += bv[c + 2]; v.w += bv[c + 3];
                    v.x = v.x > 0.f ? v.x : 0.01f * v.x;
                    v.y = v.y > 0.f ? v.y : 0.01f * v.y;
                    v.z = v.z > 0.f ? v.z : 0.01f * v.z;
                    v.w = v.w > 0.f ? v.w : 0.01f * v.w;
                }
                *(float4*)(Crow + c) = v;
            }
        }
    }
}

// ---------------------------------------------------------------------------
// Per-row double dot: o1[i] = Hs[i]·a1, o2[i] = Hs[i]·a2.  One warp per row.
// ---------------------------------------------------------------------------
__global__ void rowdots_kernel(const float* __restrict__ Hs,
                               const float* __restrict__ a1,
                               const float* __restrict__ a2,
                               float* __restrict__ o1, float* __restrict__ o2, int M)
{
    int gt = blockIdx.x * blockDim.x + threadIdx.x;
    int w = gt >> 5;
    int lane = gt & 31;
    if (w >= M) return;
    float4 v = ((const float4*)(Hs + (size_t)w * HC))[lane];
    float4 x = ((const float4*)a1)[lane];
    float4 y = ((const float4*)a2)[lane];
    float s1 = v.x * x.x + v.y * x.y + v.z * x.z + v.w * x.w;
    float s2 = v.x * y.x + v.y * y.y + v.z * y.z + v.w * y.w;
#pragma unroll
    for (int o = 16; o; o >>= 1) {
        s1 += __shfl_xor_sync(0xFFFFFFFFu, s1, o);
        s2 += __shfl_xor_sync(0xFFFFFFFFu, s2, o);
    }
    if (lane == 0) { o1[w] = s1; o2[w] = s2; }
}

__global__ void fill_kernel(float* p, float v, int n)
{
    int i = blockIdx.x * blockDim.x + threadIdx.x;
    if (i < n) p[i] = v;
}

// ---------------------------------------------------------------------------
// Edge pass 1: e = leaky(as[src]+ad[dst]); ex = exp(e); denom[dst] += ex
// (No max-subtraction needed: alpha = ex/denom is invariant; e ~ N(0,~2).)
// ---------------------------------------------------------------------------
__global__ void edge_exp_kernel(const void* __restrict__ ei,
                                const float* __restrict__ as_n,
                                const float* __restrict__ ad_n,
                                float* __restrict__ ex, float* __restrict__ den)
{
    int e = blockIdx.x * blockDim.x + threadIdx.x;
    if (e >= N_EDGESC) return;
    int s = load_edge_idx(ei, e);
    int d = load_edge_idx(ei, e + N_EDGESC);
    float v = as_n[s] + ad_n[d];
    v = v > 0.f ? v : 0.01f * v;
    v = fminf(v, 80.f);
    float x = expf(v);
    ex[e] = x;
    atomicAdd(&den[d], x);
}

// ---------------------------------------------------------------------------
// Edge pass 2: acc[dst] += (ex/denom[dst]) * hs[src].  One warp per edge,
// each lane handles 4 contiguous columns via red.global.add.v4.f32.
// ---------------------------------------------------------------------------
__global__ void edge_scatter_kernel(const void* __restrict__ ei,
                                    const float* __restrict__ Hs,
                                    const float* __restrict__ ex,
                                    const float* __restrict__ den,
                                    float* __restrict__ acc)
{
    int gt = blockIdx.x * blockDim.x + threadIdx.x;
    int e = gt >> 5;
    int lane = gt & 31;
    if (e >= N_EDGESC) return;
    int s = load_edge_idx(ei, e);
    int d = load_edge_idx(ei, e + N_EDGESC);
    float alpha = ex[e] / den[d];
    float4 v = ((const float4*)(Hs + (size_t)s * HC))[lane];
    v.x *= alpha; v.y *= alpha; v.z *= alpha; v.w *= alpha;
    float* dst = acc + (size_t)d * HC + lane * 4;
    asm volatile("red.global.add.v4.f32 [%0], {%1,%2,%3,%4};"
                 :: "l"(dst), "f"(v.x), "f"(v.y), "f"(v.z), "f"(v.w) : "memory");
}

// h_out = elu(acc + b)   (per-element, b broadcast over columns)
__global__ void bias_elu_kernel(const float* __restrict__ acc,
                                const float* __restrict__ b,
                                float* __restrict__ out, int total)
{
    int i = blockIdx.x * blockDim.x + threadIdx.x;
    if (i >= total) return;
    int c = i & (HC - 1);
    float v = acc[i] + b[c];
    out[i] = v > 0.f ? v : expm1f(v);
}

// pooled[batch[n]] += h[n]   (one warp per node, v4 reductions)
__global__ void pool_scatter_kernel(const void* __restrict__ bp,
                                    const float* __restrict__ Hn,
                                    float* __restrict__ pooled)
{
    int gt = blockIdx.x * blockDim.x + threadIdx.x;
    int n = gt >> 5;
    int lane = gt & 31;
    if (n >= N_NODESC) return;
    int b = load_batch_idx(bp, n);
    float4 v = ((const float4*)(Hn + (size_t)n * HC))[lane];
    float* dst = pooled + (size_t)b * HC + lane * 4;
    asm volatile("red.global.add.v4.f32 [%0], {%1,%2,%3,%4};"
                 :: "l"(dst), "f"(v.x), "f"(v.y), "f"(v.z), "f"(v.w) : "memory");
}

__global__ void relu_kernel(float* p, int n)
{
    int i = blockIdx.x * blockDim.x + threadIdx.x;
    if (i < n) p[i] = fmaxf(p[i], 0.f);
}

// Bipartite attention pass 1 over node->graph edges (i, batch[i])
__global__ void pool_edge_exp_kernel(const void* __restrict__ bp,
                                     const float* __restrict__ as_n,
                                     const float* __restrict__ adg,
                                     float* __restrict__ ex, float* __restrict__ den)
{
    int i = blockIdx.x * blockDim.x + threadIdx.x;
    if (i >= N_NODESC) return;
    int b = load_batch_idx(bp, i);
    float v = as_n[i] + adg[b];
    v = v > 0.f ? v : 0.01f * v;
    v = fminf(v, 80.f);
    float x = expf(v);
    ex[i] = x;
    atomicAdd(&den[b], x);
}

// Bipartite pass 2: gacc[batch[i]] += alpha_i * hs[i]
__global__ void pool_edge_scatter_kernel(const void* __restrict__ bp,
                                         const float* __restrict__ Hs,
                                         const float* __restrict__ ex,
                                         const float* __restrict__ den,
                                         float* __restrict__ gacc)
{
    int gt = blockIdx.x * blockDim.x + threadIdx.x;
    int n = gt >> 5;
    int lane = gt & 31;
    if (n >= N_NODESC) return;
    int b = load_batch_idx(bp, n);
    float alpha = ex[n] / den[b];
    float4 v = ((const float4*)(Hs + (size_t)n * HC))[lane];
    v.x *= alpha; v.y *= alpha; v.z *= alpha; v.w *= alpha;
    float* dst = gacc + (size_t)b * HC + lane * 4;
    asm volatile("red.global.add.v4.f32 [%0], {%1,%2,%3,%4};"
                 :: "l"(dst), "f"(v.x), "f"(v.y), "f"(v.z), "f"(v.w) : "memory");
}

// out[g] = elu(gacc[g] + m_b) · W2 + b2   (one warp per graph)
__global__ void final_kernel(const float* __restrict__ gacc,
                             const float* __restrict__ mb,
                             const float* __restrict__ W2,
                             const float* __restrict__ b2,
                             float* __restrict__ out)
{
    int gt = blockIdx.x * blockDim.x + threadIdx.x;
    int g = gt >> 5;
    int lane = gt & 31;
    if (g >= N_GRAPHSC) return;
    float4 a = ((const float4*)(gacc + (size_t)g * HC))[lane];
    float4 bb = ((const float4*)mb)[lane];
    float4 w2 = ((const float4*)W2)[lane];
    a.x += bb.x; a.y += bb.y; a.z += bb.z; a.w += bb.w;
    a.x = a.x > 0.f ? a.x : expm1f(a.x);
    a.y = a.y > 0.f ? a.y : expm1f(a.y);
    a.z = a.z > 0.f ? a.z : expm1f(a.z);
    a.w = a.w > 0.f ? a.w : expm1f(a.w);
    float s = a.x * w2.x + a.y * w2.y + a.z * w2.z + a.w * w2.w;
#pragma unroll
    for (int o = 16; o; o >>= 1) s += __shfl_xor_sync(0xFFFFFFFFu, s, o);
    if (lane == 0) out[g] = s + b2[0];
}

// ---------------------------------------------------------------------------
// Host launcher
// ---------------------------------------------------------------------------
extern "C" void kernel_launch(void* const* d_in, const int* in_sizes, int n_in,
                              void* d_out, int out_size)
{
    (void)in_sizes; (void)n_in; (void)out_size;
    const float* x     = (const float*)d_in[0];
    const void*  ei    = d_in[1];
    const void*  batch = d_in[2];
    const float* W1    = (const float*)d_in[3];
    const float* b1    = (const float*)d_in[4];
    const float* gW    = (const float*)d_in[5];
    const float* gasrc = (const float*)d_in[6];
    const float* gadst = (const float*)d_in[7];
    const float* gb    = (const float*)d_in[8];
    const float* mW    = (const float*)d_in[9];
    const float* masrc = (const float*)d_in[10];
    const float* madst = (const float*)d_in[11];
    const float* mb    = (const float*)d_in[12];
    const float* W2    = (const float*)d_in[13];
    const float* b2    = (const float*)d_in[14];
    float* out = (float*)d_out;

    float *h, *hs, *acc, *as_, *ad_, *ex, *den, *pooled, *hd, *gacc, *asg, *adg;
    cudaGetSymbolAddress((void**)&h,      g_h);
    cudaGetSymbolAddress((void**)&hs,     g_hs);
    cudaGetSymbolAddress((void**)&acc,    g_acc);
    cudaGetSymbolAddress((void**)&as_,    g_as);
    cudaGetSymbolAddress((void**)&ad_,    g_ad);
    cudaGetSymbolAddress((void**)&ex,     g_ex);
    cudaGetSymbolAddress((void**)&den,    g_den);
    cudaGetSymbolAddress((void**)&pooled, g_pooled);
    cudaGetSymbolAddress((void**)&hd,     g_hd);
    cudaGetSymbolAddress((void**)&gacc,   g_gacc);
    cudaGetSymbolAddress((void**)&asg,    g_asg);
    cudaGetSymbolAddress((void**)&adg,    g_adg);

    const int T = 256;
    const int nodeWarpBlocks  = (N_NODESC * 32 + T - 1) / T;
    const int edgeWarpBlocks  = (N_EDGESC * 32 + T - 1) / T;
    const int graphWarpBlocks = (N_GRAPHSC * 32 + T - 1) / T;
    const int elemBlocks      = ((int)((size_t)N_NODESC * HC) + T - 1) / T;

    // 0. dtype detection (int64 vs int32 indices)
    detect_kernel<<<1, 256>>>(ei, batch);

    // 1. h = leaky_relu(x @ W1 + b1)
    gemm_kernel<F_INC, 1><<<(N_NODESC + 63) / 64, T>>>(x, W1, b1, h, N_NODESC);

    // 2. three GAT layers
    for (int i = 0; i < 3; i++) {
        gemm_kernel<HC, 0><<<(N_NODESC + 63) / 64, T>>>(h, gW + (size_t)i * HC * HC, nullptr, hs, N_NODESC);
        rowdots_kernel<<<nodeWarpBlocks, T>>>(hs, gasrc + i * HC, gadst + i * HC, as_, ad_, N_NODESC);
        cudaMemsetAsync(acc, 0, (size_t)N_NODESC * HC * sizeof(float));
        fill_kernel<<<(N_NODESC + T - 1) / T, T>>>(den, 1e-16f, N_NODESC);
        edge_exp_kernel<<<(N_EDGESC + T - 1) / T, T>>>(ei, as_, ad_, ex, den);
        edge_scatter_kernel<<<edgeWarpBlocks, T>>>(ei, hs, ex, den, acc);
        bias_elu_kernel<<<elemBlocks, T>>>(acc, gb + i * HC, h, (int)((size_t)N_NODESC * HC));
    }

    // 3. pooled = relu(segment_sum(h, batch))
    cudaMemsetAsync(pooled, 0, (size_t)N_GRAPHSC * HC * sizeof(float));
    pool_scatter_kernel<<<nodeWarpBlocks, T>>>(batch, h, pooled);
    relu_kernel<<<(N_GRAPHSC * HC + T - 1) / T, T>>>(pooled, N_GRAPHSC * HC);

    // 4. bipartite GAT readout
    gemm_kernel<HC, 0><<<(N_NODESC + 63) / 64, T>>>(h, mW, nullptr, hs, N_NODESC);
    gemm_kernel<HC, 0><<<(N_GRAPHSC + 63) / 64, T>>>(pooled, mW, nullptr, hd, N_GRAPHSC);
    rowdots_kernel<<<nodeWarpBlocks, T>>>(hs, masrc, madst, as_, ad_, N_NODESC);     // need as_
    rowdots_kernel<<<graphWarpBlocks, T>>>(hd, masrc, madst, asg, adg, N_GRAPHSC);   // need adg
    cudaMemsetAsync(gacc, 0, (size_t)N_GRAPHSC * HC * sizeof(float));
    fill_kernel<<<(N_GRAPHSC + T - 1) / T, T>>>(den, 1e-16f, N_GRAPHSC);
    pool_edge_exp_kernel<<<(N_NODESC + T - 1) / T, T>>>(batch, as_, adg, ex, den);
    pool_edge_scatter_kernel<<<nodeWarpBlocks, T>>>(batch, hs, ex, den, gacc);

    // 5. out = elu(gacc + m_b) @ W2 + b2
    final_kernel<<<graphWarpBlocks, T>>>(gacc, mb, W2, b2, out);
}

// round 4
// speedup vs baseline: 1.6216x; 1.6216x over previous
#include <cuda_runtime.h>
#include <cstdint>
#include <math.h>

#define N_NODESC 100000
#define N_EDGESC 400000
#define N_GRAPHSC 5000
#define F_INC 64
#define HC 128

// ---------------------------------------------------------------------------
// Scratch
// ---------------------------------------------------------------------------
__device__ __align__(16) float g_h   [(size_t)N_NODESC * HC];
__device__ __align__(16) float g_hs  [(size_t)N_NODESC * HC];
__device__ __align__(16) float g_acc [(size_t)N_NODESC * HC];
__device__ __align__(16) float g_as  [N_NODESC];
__device__ __align__(16) float g_ad  [N_NODESC];
__device__ __align__(16) float g_den [N_NODESC];
__device__ __align__(16) float g_pooled[(size_t)N_GRAPHSC * HC];
__device__ __align__(16) float g_hd    [(size_t)N_GRAPHSC * HC];
__device__ __align__(16) float g_gacc  [(size_t)N_GRAPHSC * HC];
__device__ __align__(16) float g_asg [N_GRAPHSC];
__device__ __align__(16) float g_adg [N_GRAPHSC];
__device__ int g_i64flag[2];

// ---------------------------------------------------------------------------
// dtype detection (int64 vs int32 indices)
// ---------------------------------------------------------------------------
__global__ void detect_kernel(const void* ei, const void* batch)
{
    int t = threadIdx.x;
    const long long* p = (const long long*)ei;
    const long long* q = (const long long*)batch;
    long long v1 = p[t];
    long long v2 = q[t];
    int bad1 = (v1 < 0 || v1 >= N_NODESC) ? 1 : 0;
    int bad2 = (v2 < 0 || v2 >= N_GRAPHSC) ? 1 : 0;
    int any1 = __syncthreads_or(bad1);
    int any2 = __syncthreads_or(bad2);
    if (t == 0) { g_i64flag[0] = any1 ? 0 : 1; g_i64flag[1] = any2 ? 0 : 1; }
}
__device__ __forceinline__ int load_edge_idx(const void* ei, int i)
{
    if (g_i64flag[0]) return (int)((const long long*)ei)[i];
    return ((const int*)ei)[i];
}
__device__ __forceinline__ int load_batch_idx(const void* bp, int i)
{
    if (g_i64flag[1]) return (int)((const long long*)bp)[i];
    return ((const int*)bp)[i];
}

// ---------------------------------------------------------------------------
// TF32 helpers
// ---------------------------------------------------------------------------
__device__ __forceinline__ void tf32_split(float v, float& hi, float& lo)
{
    uint32_t hb; asm("cvt.rna.tf32.f32 %0, %1;" : "=r"(hb) : "f"(v));
    hi = __uint_as_float(hb);
    float l = v - hi;                       // exact in fp32
    uint32_t lb; asm("cvt.rna.tf32.f32 %0, %1;" : "=r"(lb) : "f"(l));
    lo = __uint_as_float(lb);
}

__device__ __forceinline__ void mma_tf32(float* c, const uint32_t* a, const uint32_t* b)
{
    asm volatile(
        "mma.sync.aligned.m16n8k8.row.col.f32.tf32.tf32.f32 "
        "{%0,%1,%2,%3}, {%4,%5,%6,%7}, {%8,%9}, {%0,%1,%2,%3};"
        : "+f"(c[0]), "+f"(c[1]), "+f"(c[2]), "+f"(c[3])
        : "r"(a[0]), "r"(a[1]), "r"(a[2]), "r"(a[3]), "r"(b[0]), "r"(b[1]));
}

// ---------------------------------------------------------------------------
// 3xTF32 GEMM: C[M,128] = A[M,K] @ W[K,128]
// Block: 256 threads, tile 128x128, BK=16. Warp (w): rows (w>>1)*32..+31,
// cols (w&1)*64..+63 via 2 m-tiles x 8 n-tiles of m16n8k8.
// ACT=1: +bias, leaky_relu(0.01). DOTS=1: also emit o1=C.a1, o2=C.a2 per row.
// 3xTF32: C += Ahi*Whi + Ahi*Wlo + Alo*Whi  (fp32-grade accuracy)
// ---------------------------------------------------------------------------
#define BKX 16
#define APAD 20
#define WPAD 132

template<int K, int ACT, int DOTS>
__global__ __launch_bounds__(256, 2)
void gemm_tf32_kernel(const float* __restrict__ A, const float* __restrict__ W,
                      const float* __restrict__ bias, float* __restrict__ Cout,
                      float* __restrict__ o1, float* __restrict__ o2,
                      const float* __restrict__ a1, const float* __restrict__ a2,
                      int M)
{
    __shared__ float Ahi[128][APAD], Alo[128][APAD];   // 20.0 KB
    __shared__ float Whi[BKX][WPAD], Wlo[BKX][WPAD];   // 16.5 KB
    __shared__ float asrc_s[HC], adst_s[HC];
    __shared__ float as_s[128], ad_s[128];

    int t = threadIdx.x;
    int wid = t >> 5;
    int lane = t & 31;
    int g = lane >> 2;          // 0..7
    int t4 = lane & 3;          // 0..3
    int mBase = (wid >> 1) * 32;
    int nWarp = (wid & 1) * 64;
    int row0 = blockIdx.x * 128;

    if (DOTS) {
        if (t < 128) { asrc_s[t] = a1[t]; adst_s[t] = a2[t]; as_s[t] = 0.f; ad_s[t] = 0.f; }
    }

    float Cf[2][8][4];
#pragma unroll
    for (int mt = 0; mt < 2; mt++)
#pragma unroll
        for (int nt = 0; nt < 8; nt++)
#pragma unroll
            for (int i = 0; i < 4; i++) Cf[mt][nt][i] = 0.f;

    for (int kc = 0; kc < K; kc += BKX) {
        // W chunk 16x128: 512 float4, 2 per thread
#pragma unroll
        for (int it = 0; it < 2; it++) {
            int i = t + it * 256;
            int r = i >> 5, c4 = (i & 31) * 4;
            float4 v = *(const float4*)(W + (size_t)(kc + r) * HC + c4);
            float h0, l0, h1, l1, h2, l2, h3, l3;
            tf32_split(v.x, h0, l0); tf32_split(v.y, h1, l1);
            tf32_split(v.z, h2, l2); tf32_split(v.w, h3, l3);
            *(float4*)(&Whi[r][c4]) = make_float4(h0, h1, h2, h3);
            *(float4*)(&Wlo[r][c4]) = make_float4(l0, l1, l2, l3);
        }
        // A chunk 128x16: 512 float4, 2 per thread
#pragma unroll
        for (int it = 0; it < 2; it++) {
            int i = t + it * 256;
            int r = i >> 2, j = (i & 3) * 4;
            int row = row0 + r;
            float4 v = make_float4(0.f, 0.f, 0.f, 0.f);
            if (row < M) v = *(const float4*)(A + (size_t)row * K + kc + j);
            float h0, l0, h1, l1, h2, l2, h3, l3;
            tf32_split(v.x, h0, l0); tf32_split(v.y, h1, l1);
            tf32_split(v.z, h2, l2); tf32_split(v.w, h3, l3);
            *(float4*)(&Ahi[r][j]) = make_float4(h0, h1, h2, h3);
            *(float4*)(&Alo[r][j]) = make_float4(l0, l1, l2, l3);
        }
        __syncthreads();

#pragma unroll
        for (int k8 = 0; k8 < BKX; k8 += 8) {
            uint32_t ah[2][4], al[2][4];
#pragma unroll
            for (int mt = 0; mt < 2; mt++) {
                int wr = mBase + mt * 16 + g;
                ah[mt][0] = __float_as_uint(Ahi[wr][k8 + t4]);
                ah[mt][1] = __float_as_uint(Ahi[wr + 8][k8 + t4]);
                ah[mt][2] = __float_as_uint(Ahi[wr][k8 + t4 + 4]);
                ah[mt][3] = __float_as_uint(Ahi[wr + 8][k8 + t4 + 4]);
                al[mt][0] = __float_as_uint(Alo[wr][k8 + t4]);
                al[mt][1] = __float_as_uint(Alo[wr + 8][k8 + t4]);
                al[mt][2] = __float_as_uint(Alo[wr][k8 + t4 + 4]);
                al[mt][3] = __float_as_uint(Alo[wr + 8][k8 + t4 + 4]);
            }
#pragma unroll
            for (int nt = 0; nt < 8; nt++) {
                int cn = nWarp + nt * 8 + g;
                uint32_t bh[2], bl[2];
                bh[0] = __float_as_uint(Whi[k8 + t4][cn]);
                bh[1] = __float_as_uint(Whi[k8 + t4 + 4][cn]);
                bl[0] = __float_as_uint(Wlo[k8 + t4][cn]);
                bl[1] = __float_as_uint(Wlo[k8 + t4 + 4][cn]);
                mma_tf32(Cf[0][nt], ah[0], bh);
                mma_tf32(Cf[1][nt], ah[1], bh);
                mma_tf32(Cf[0][nt], ah[0], bl);
                mma_tf32(Cf[1][nt], ah[1], bl);
                mma_tf32(Cf[0][nt], al[0], bh);
                mma_tf32(Cf[1][nt], al[1], bh);
            }
        }
        __syncthreads();
    }

    // epilogue: store C (+ACT), optional fused row-dots
#pragma unroll
    for (int mt = 0; mt < 2; mt++) {
        int rowA = row0 + mBase + mt * 16 + g;
        int rowB = rowA + 8;
#pragma unroll
        for (int nt = 0; nt < 8; nt++) {
            int col = nWarp + nt * 8 + 2 * t4;
            float c0 = Cf[mt][nt][0], c1 = Cf[mt][nt][1];
            float c2 = Cf[mt][nt][2], c3 = Cf[mt][nt][3];
            if (ACT) {
                float b0 = __ldg(bias + col), b1 = __ldg(bias + col + 1);
                c0 += b0; c1 += b1; c2 += b0; c3 += b1;
                c0 = c0 > 0.f ? c0 : 0.01f * c0;
                c1 = c1 > 0.f ? c1 : 0.01f * c1;
                c2 = c2 > 0.f ? c2 : 0.01f * c2;
                c3 = c3 > 0.f ? c3 : 0.01f * c3;
            }
            if (rowA < M) *(float2*)(Cout + (size_t)rowA * HC + col) = make_float2(c0, c1);
            if (rowB < M) *(float2*)(Cout + (size_t)rowB * HC + col) = make_float2(c2, c3);
        }
        if (DOTS) {
            float s1a = 0.f, s2a = 0.f, s1b = 0.f, s2b = 0.f;
#pragma unroll
            for (int nt = 0; nt < 8; nt++) {
                int col = nWarp + nt * 8 + 2 * t4;
                float w10 = asrc_s[col], w11 = asrc_s[col + 1];
                float w20 = adst_s[col], w21 = adst_s[col + 1];
                s1a += Cf[mt][nt][0] * w10 + Cf[mt][nt][1] * w11;
                s2a += Cf[mt][nt][0] * w20 + Cf[mt][nt][1] * w21;
                s1b += Cf[mt][nt][2] * w10 + Cf[mt][nt][3] * w11;
                s2b += Cf[mt][nt][2] * w20 + Cf[mt][nt][3] * w21;
            }
            atomicAdd(&as_s[mBase + mt * 16 + g], s1a);
            atomicAdd(&ad_s[mBase + mt * 16 + g], s2a);
            atomicAdd(&as_s[mBase + mt * 16 + g + 8], s1b);
            atomicAdd(&ad_s[mBase + mt * 16 + g + 8], s2b);
        }
    }
    if (DOTS) {
        __syncthreads();
        if (t < 128) {
            int row = row0 + t;
            if (row < M) { o1[row] = as_s[t]; o2[row] = ad_s[t]; }
        }
    }
}

__global__ void fill_kernel(float* p, float v, int n)
{
    int i = blockIdx.x * blockDim.x + threadIdx.x;
    if (i < n) p[i] = v;
}

// ---------------------------------------------------------------------------
// Fused edge pass: x = exp(leaky(as[s]+ad[d])); den[d]+=x; acc[d]+=x*hs[s]
// (unnormalized scatter; normalization in bias_elu_div — mathematically
//  identical to alpha-normalized sum)
// ---------------------------------------------------------------------------
__global__ void edge_fused_kernel(const void* __restrict__ ei,
                                  const float* __restrict__ as_n,
                                  const float* __restrict__ ad_n,
                                  const float* __restrict__ Hs,
                                  float* __restrict__ acc,
                                  float* __restrict__ den)
{
    int gt = blockIdx.x * blockDim.x + threadIdx.x;
    int e = gt >> 5;
    int lane = gt & 31;
    if (e >= N_EDGESC) return;
    int s = load_edge_idx(ei, e);
    int d = load_edge_idx(ei, e + N_EDGESC);
    float v = as_n[s] + ad_n[d];
    v = v > 0.f ? v : 0.01f * v;
    v = fminf(v, 80.f);
    float x = __expf(v);
    if (lane == 0)
        asm volatile("red.global.add.f32 [%0], %1;" :: "l"(den + d), "f"(x) : "memory");
    float4 hv = ((const float4*)(Hs + (size_t)s * HC))[lane];
    hv.x *= x; hv.y *= x; hv.z *= x; hv.w *= x;
    float* dst = acc + (size_t)d * HC + lane * 4;
    asm volatile("red.global.add.v4.f32 [%0], {%1,%2,%3,%4};"
                 :: "l"(dst), "f"(hv.x), "f"(hv.y), "f"(hv.z), "f"(hv.w) : "memory");
}

// h = elu(acc/den + b)   (warp per row; one reciprocal per warp)
__global__ void bias_elu_div_kernel(const float* __restrict__ acc,
                                    const float* __restrict__ den,
                                    const float* __restrict__ b,
                                    float* __restrict__ out, int M)
{
    int gt = blockIdx.x * blockDim.x + threadIdx.x;
    int row = gt >> 5;
    int lane = gt & 31;
    if (row >= M) return;
    float r = 0.f;
    if (lane == 0) r = 1.f / den[row];
    r = __shfl_sync(0xFFFFFFFFu, r, 0);
    float4 a = ((const float4*)(acc + (size_t)row * HC))[lane];
    float4 bb = ((const float4*)b)[lane];
    a.x = a.x * r + bb.x; a.y = a.y * r + bb.y;
    a.z = a.z * r + bb.z; a.w = a.w * r + bb.w;
    a.x = a.x > 0.f ? a.x : __expf(a.x) - 1.f;
    a.y = a.y > 0.f ? a.y : __expf(a.y) - 1.f;
    a.z = a.z > 0.f ? a.z : __expf(a.z) - 1.f;
    a.w = a.w > 0.f ? a.w : __expf(a.w) - 1.f;
    ((float4*)(out + (size_t)row * HC))[lane] = a;
}

// pooled[batch[n]] += h[n]
__global__ void pool_scatter_kernel(const void* __restrict__ bp,
                                    const float* __restrict__ Hn,
                                    float* __restrict__ pooled)
{
    int gt = blockIdx.x * blockDim.x + threadIdx.x;
    int n = gt >> 5;
    int lane = gt & 31;
    if (n >= N_NODESC) return;
    int b = load_batch_idx(bp, n);
    float4 v = ((const float4*)(Hn + (size_t)n * HC))[lane];
    float* dst = pooled + (size_t)b * HC + lane * 4;
    asm volatile("red.global.add.v4.f32 [%0], {%1,%2,%3,%4};"
                 :: "l"(dst), "f"(v.x), "f"(v.y), "f"(v.z), "f"(v.w) : "memory");
}

__global__ void relu_kernel(float* p, int n)
{
    int i = blockIdx.x * blockDim.x + threadIdx.x;
    if (i < n) p[i] = fmaxf(p[i], 0.f);
}

// Fused bipartite pass: x=exp(leaky(as[n]+adg[b])); den[b]+=x; gacc[b]+=x*hs[n]
__global__ void pool_fused_kernel(const void* __restrict__ bp,
                                  const float* __restrict__ as_n,
                                  const float* __restrict__ adg,
                                  const float* __restrict__ Hs,
                                  float* __restrict__ gacc,
                                  float* __restrict__ den)
{
    int gt = blockIdx.x * blockDim.x + threadIdx.x;
    int n = gt >> 5;
    int lane = gt & 31;
    if (n >= N_NODESC) return;
    int b = load_batch_idx(bp, n);
    float v = as_n[n] + adg[b];
    v = v > 0.f ? v : 0.01f * v;
    v = fminf(v, 80.f);
    float x = __expf(v);
    if (lane == 0)
        asm volatile("red.global.add.f32 [%0], %1;" :: "l"(den + b), "f"(x) : "memory");
    float4 hv = ((const float4*)(Hs + (size_t)n * HC))[lane];
    hv.x *= x; hv.y *= x; hv.z *= x; hv.w *= x;
    float* dst = gacc + (size_t)b * HC + lane * 4;
    asm volatile("red.global.add.v4.f32 [%0], {%1,%2,%3,%4};"
                 :: "l"(dst), "f"(hv.x), "f"(hv.y), "f"(hv.z), "f"(hv.w) : "memory");
}

// out[g] = elu(gacc[g]/den[g] + m_b) · W2 + b2
__global__ void final_kernel(const float* __restrict__ gacc,
                             const float* __restrict__ den,
                             const float* __restrict__ mb,
                             const float* __restrict__ W2,
                             const float* __restrict__ b2,
                             float* __restrict__ out)
{
    int gt = blockIdx.x * blockDim.x + threadIdx.x;
    int g = gt >> 5;
    int lane = gt & 31;
    if (g >= N_GRAPHSC) return;
    float r = 0.f;
    if (lane == 0) r = 1.f / den[g];
    r = __shfl_sync(0xFFFFFFFFu, r, 0);
    float4 a = ((const float4*)(gacc + (size_t)g * HC))[lane];
    float4 bb = ((const float4*)mb)[lane];
    float4 w2 = ((const float4*)W2)[lane];
    a.x = a.x * r + bb.x; a.y = a.y * r + bb.y;
    a.z = a.z * r + bb.z; a.w = a.w * r + bb.w;
    a.x = a.x > 0.f ? a.x : __expf(a.x) - 1.f;
    a.y = a.y > 0.f ? a.y : __expf(a.y) - 1.f;
    a.z = a.z > 0.f ? a.z : __expf(a.z) - 1.f;
    a.w = a.w > 0.f ? a.w : __expf(a.w) - 1.f;
    float s = a.x * w2.x + a.y * w2.y + a.z * w2.z + a.w * w2.w;
#pragma unroll
    for (int o = 16; o; o >>= 1) s += __shfl_xor_sync(0xFFFFFFFFu, s, o);
    if (lane == 0) out[g] = s + b2[0];
}

// ---------------------------------------------------------------------------
// Host launcher
// ---------------------------------------------------------------------------
extern "C" void kernel_launch(void* const* d_in, const int* in_sizes, int n_in,
                              void* d_out, int out_size)
{
    (void)in_sizes; (void)n_in; (void)out_size;
    const float* x     = (const float*)d_in[0];
    const void*  ei    = d_in[1];
    const void*  batch = d_in[2];
    const float* W1    = (const float*)d_in[3];
    const float* b1    = (const float*)d_in[4];
    const float* gW    = (const float*)d_in[5];
    const float* gasrc = (const float*)d_in[6];
    const float* gadst = (const float*)d_in[7];
    const float* gb    = (const float*)d_in[8];
    const float* mW    = (const float*)d_in[9];
    const float* masrc = (const float*)d_in[10];
    const float* madst = (const float*)d_in[11];
    const float* mb    = (const float*)d_in[12];
    const float* W2    = (const float*)d_in[13];
    const float* b2    = (const float*)d_in[14];
    float* out = (float*)d_out;

    float *h, *hs, *acc, *as_, *ad_, *den, *pooled, *hd, *gacc, *asg, *adg;
    cudaGetSymbolAddress((void**)&h,      g_h);
    cudaGetSymbolAddress((void**)&hs,     g_hs);
    cudaGetSymbolAddress((void**)&acc,    g_acc);
    cudaGetSymbolAddress((void**)&as_,    g_as);
    cudaGetSymbolAddress((void**)&ad_,    g_ad);
    cudaGetSymbolAddress((void**)&den,    g_den);
    cudaGetSymbolAddress((void**)&pooled, g_pooled);
    cudaGetSymbolAddress((void**)&hd,     g_hd);
    cudaGetSymbolAddress((void**)&gacc,   g_gacc);
    cudaGetSymbolAddress((void**)&asg,    g_asg);
    cudaGetSymbolAddress((void**)&adg,    g_adg);

    const int T = 256;
    const int nodeWarpBlocks  = (N_NODESC * 32 + T - 1) / T;
    const int edgeWarpBlocks  = (N_EDGESC * 32 + T - 1) / T;
    const int graphWarpBlocks = (N_GRAPHSC * 32 + T - 1) / T;
    const int gemmBlocksN = (N_NODESC + 127) / 128;
    const int gemmBlocksG = (N_GRAPHSC + 127) / 128;

    detect_kernel<<<1, 256>>>(ei, batch);

    // 1. h = leaky_relu(x @ W1 + b1)
    gemm_tf32_kernel<F_INC, 1, 0><<<gemmBlocksN, T>>>(
        x, W1, b1, h, nullptr, nullptr, nullptr, nullptr, N_NODESC);

    // 2. three GAT layers
    for (int i = 0; i < 3; i++) {
        gemm_tf32_kernel<HC, 0, 1><<<gemmBlocksN, T>>>(
            h, gW + (size_t)i * HC * HC, nullptr, hs,
            as_, ad_, gasrc + i * HC, gadst + i * HC, N_NODESC);
        cudaMemsetAsync(acc, 0, (size_t)N_NODESC * HC * sizeof(float));
        fill_kernel<<<(N_NODESC + T - 1) / T, T>>>(den, 1e-16f, N_NODESC);
        edge_fused_kernel<<<edgeWarpBlocks, T>>>(ei, as_, ad_, hs, acc, den);
        bias_elu_div_kernel<<<nodeWarpBlocks, T>>>(acc, den, gb + i * HC, h, N_NODESC);
    }

    // 3. pooled = relu(segment_sum(h, batch))
    cudaMemsetAsync(pooled, 0, (size_t)N_GRAPHSC * HC * sizeof(float));
    pool_scatter_kernel<<<nodeWarpBlocks, T>>>(batch, h, pooled);
    relu_kernel<<<(N_GRAPHSC * HC + T - 1) / T, T>>>(pooled, N_GRAPHSC * HC);

    // 4. bipartite GAT readout
    gemm_tf32_kernel<HC, 0, 1><<<gemmBlocksN, T>>>(
        h, mW, nullptr, hs, as_, ad_, masrc, madst, N_NODESC);
    gemm_tf32_kernel<HC, 0, 1><<<gemmBlocksG, T>>>(
        pooled, mW, nullptr, hd, asg, adg, masrc, madst, N_GRAPHSC);
    cudaMemsetAsync(gacc, 0, (size_t)N_GRAPHSC * HC * sizeof(float));
    fill_kernel<<<(N_GRAPHSC + T - 1) / T, T>>>(den, 1e-16f, N_GRAPHSC);
    pool_fused_kernel<<<nodeWarpBlocks, T>>>(batch, as_, adg, hs, gacc, den);

    // 5. out
    final_kernel<<<graphWarpBlocks, T>>>(gacc, den, mb, W2, b2, out);
}